// round 14
// baseline (speedup 1.0000x reference)
#include <cuda_runtime.h>
#include <cuda_bf16.h>
#include <cstdint>

#define N_NODES 50000
#define E_EDGES 800000
#define DIN 128
#define DH 256
#define P_PAIRS 100000
#define M_PRED (2 * P_PAIRS)

// ================= helpers =====================================================
__device__ __forceinline__ uint32_t smem_u32(const void* p) {
    uint32_t a;
    asm("{ .reg .u64 t; cvta.to.shared.u64 t, %1; cvt.u32.u64 %0, t; }" : "=r"(a) : "l"(p));
    return a;
}
__device__ __forceinline__ void cp16(uint32_t dst, const void* src, uint32_t sz) {
    asm volatile("cp.async.cg.shared.global [%0], [%1], 16, %2;"
                 :: "r"(dst), "l"(src), "r"(sz) : "memory");
}
__device__ __forceinline__ void cp_commit() {
    asm volatile("cp.async.commit_group;" ::: "memory");
}
#define CP_WAIT(n) asm volatile("cp.async.wait_group %0;" :: "n"(n) : "memory")

__device__ __forceinline__ void ldsm4(uint32_t* r, uint32_t addr) {
    asm volatile("ldmatrix.sync.aligned.m8n8.x4.shared.b16 {%0,%1,%2,%3}, [%4];"
                 : "=r"(r[0]), "=r"(r[1]), "=r"(r[2]), "=r"(r[3]) : "r"(addr));
}
__device__ __forceinline__ void mma_bf16(float* d, const uint32_t* a, const uint32_t* b) {
    asm volatile(
        "mma.sync.aligned.m16n8k16.row.col.f32.bf16.bf16.f32 "
        "{%0,%1,%2,%3}, {%4,%5,%6,%7}, {%8,%9}, {%0,%1,%2,%3};"
        : "+f"(d[0]), "+f"(d[1]), "+f"(d[2]), "+f"(d[3])
        : "r"(a[0]), "r"(a[1]), "r"(a[2]), "r"(a[3]), "r"(b[0]), "r"(b[1]));
}

// split fp32 -> (hi, lo) bf16
__device__ __forceinline__ void split1(float v, uint16_t& h, uint16_t& l) {
    __nv_bfloat16 hb = __float2bfloat16_rn(v);
    float r = v - __bfloat162float(hb);
    __nv_bfloat16 lb = __float2bfloat16_rn(r);
    h = __bfloat16_as_ushort(hb);
    l = __bfloat16_as_ushort(lb);
}
__device__ __forceinline__ void split2(float v0, float v1, uint32_t& hi, uint32_t& lo) {
    uint16_t h0, l0, h1, l1;
    split1(v0, h0, l0); split1(v1, h1, l1);
    hi = (uint32_t)h0 | ((uint32_t)h1 << 16);
    lo = (uint32_t)l0 | ((uint32_t)l1 << 16);
}
__device__ __forceinline__ void split8(const float* v, uint4& hi, uint4& lo) {
    uint32_t h[4], l[4];
#pragma unroll
    for (int i = 0; i < 4; i++) split2(v[2 * i], v[2 * i + 1], h[i], l[i]);
    hi = make_uint4(h[0], h[1], h[2], h[3]);
    lo = make_uint4(l[0], l[1], l[2], l[3]);
}
__device__ __forceinline__ void unpack8(uint4 hi, uint4 lo, float* v) {
    uint32_t hw[4] = {hi.x, hi.y, hi.z, hi.w};
    uint32_t lw[4] = {lo.x, lo.y, lo.z, lo.w};
#pragma unroll
    for (int i = 0; i < 4; i++) {
        v[2 * i]     = __uint_as_float(hw[i] << 16) + __uint_as_float(lw[i] << 16);
        v[2 * i + 1] = __uint_as_float(hw[i] & 0xffff0000u) + __uint_as_float(lw[i] & 0xffff0000u);
    }
}

// Split tensor layout: row r of a [M, K] tensor occupies K*4 bytes:
//   (K/32) blocks of 128B; block = [4 x 16B hi chunks (k=0..31) | 4 x 16B lo chunks]
#define ROWB(K) ((K) * 4)

// ================= scratch =====================================================
__device__ int g_deg[N_NODES];
__device__ int g_off[N_NODES + 1];
__device__ int g_cursor[N_NODES];
__device__ int g_sorted_src[E_EDGES];
__device__ int g_bsum[64];
__device__ __align__(16) uint8_t g_xs[(size_t)N_NODES * DIN * 4];
__device__ __align__(16) uint8_t g_agg[(size_t)N_NODES * DH * 4];
__device__ __align__(16) uint8_t g_h1[(size_t)N_NODES * DH * 4];
__device__ __align__(16) uint8_t g_h2[(size_t)N_NODES * DH * 4];
__device__ __align__(16) uint8_t g_h3[(size_t)N_NODES * DH * 4];
__device__ __align__(16) uint8_t g_wt[1835008];

#define WT_WS0 0
#define WT_WN0 131072
#define WT_WS1 262144
#define WT_WN1 524288
#define WT_WS2 786432
#define WT_WN2 1048576
#define WT_WP1 1310720
#define WT_WP2 1572864

// ================= merged prep: split x + zero deg + prep W ====================
struct PrepWAll {
    const float* src[8];
    uint8_t* dst[8];
    int K[8];
};

#define PREP0_BLOCKS 3125          // (N_NODES * 16) / 256
#define PREPW_BLOCKS 256

__global__ void k_prep_all(const float* __restrict__ x, uint8_t* __restrict__ xs,
                           PrepWAll a) {
    int b = blockIdx.x;
    int t = threadIdx.x;
    if (b < PREP0_BLOCKS) {
        int i = b * 256 + t;
        if (i < N_NODES) g_deg[i] = 0;
        const int units = DIN >> 3;
        if (i < N_NODES * units) {
            int row = i / units, u = i % units;
            const float* src = x + (size_t)row * DIN + u * 8;
            float v[8];
#pragma unroll
            for (int j = 0; j < 8; j++) v[j] = src[j];
            uint4 hi, lo;
            split8(v, hi, lo);
            uint8_t* base = xs + (size_t)row * ROWB(DIN) + (u >> 2) * 128 + (u & 3) * 16;
            *(uint4*)base = hi;
            *(uint4*)(base + 64) = lo;
        }
        return;
    }
    b -= PREP0_BLOCKS;
    {
        int w = b >> 5;
        int k0 = ((b >> 2) & 7) * 32;
        int n0 = (b & 3) * 64;
        int K = a.K[w];
        if (k0 >= K) return;
        const float* src = a.src[w];
        uint8_t* dst = a.dst[w];
        __shared__ float s[32][65];
#pragma unroll
        for (int l = 0; l < 8; l++) {
            int idx = t + 256 * l;
            int i = idx >> 6, j = idx & 63;
            s[i][j] = src[(size_t)(k0 + i) * DH + n0 + j];
        }
        __syncthreads();
        int n = t >> 2, kc = t & 3;
        float v[8];
#pragma unroll
        for (int q = 0; q < 8; q++) v[q] = s[kc * 8 + q][n];
        uint4 hi, lo;
        split8(v, hi, lo);
        int k = k0 + kc * 8;
        uint8_t* base = dst + (size_t)(n0 + n) * ROWB(K) + (k >> 5) * 128 + ((k >> 3) & 3) * 16;
        *(uint4*)base = hi;
        *(uint4*)(base + 64) = lo;
    }
}

// ================= CSR build ===================================================
__global__ void k_count(const int* __restrict__ dst) {
    int e = blockIdx.x * blockDim.x + threadIdx.x;
    if (e < E_EDGES) atomicAdd(&g_deg[dst[e]], 1);
}
__global__ void k_scan_block() {
    __shared__ int s[1024];
    int i = blockIdx.x * 1024 + threadIdx.x;
    int v = (i < N_NODES) ? g_deg[i] : 0;
    s[threadIdx.x] = v;
    __syncthreads();
    for (int ofs = 1; ofs < 1024; ofs <<= 1) {
        int t = (threadIdx.x >= ofs) ? s[threadIdx.x - ofs] : 0;
        __syncthreads();
        s[threadIdx.x] += t;
        __syncthreads();
    }
    if (i < N_NODES) g_off[i] = s[threadIdx.x] - v;
    if (threadIdx.x == 1023) g_bsum[blockIdx.x] = s[1023];
}
__global__ void k_scan_add2() {
    __shared__ int sb[64];
    int tid = threadIdx.x;
    const int nb = (N_NODES + 1023) >> 10;
    if (tid < 64) sb[tid] = (tid < nb) ? g_bsum[tid] : 0;
    __syncthreads();
    for (int ofs = 1; ofs < 64; ofs <<= 1) {
        int t = 0;
        if (tid < 64 && tid >= ofs) t = sb[tid - ofs];
        __syncthreads();
        if (tid < 64) sb[tid] += t;
        __syncthreads();
    }
    int i = blockIdx.x * blockDim.x + tid;
    if (i < N_NODES) {
        int blk = i >> 10;
        int base = blk ? sb[blk - 1] : 0;
        int o = g_off[i] + base;
        g_off[i] = o;
        g_cursor[i] = o;
    }
    if (i == 0) g_off[N_NODES] = E_EDGES;
}
__global__ void k_scatter(const int* __restrict__ src, const int* __restrict__ dst) {
    int e = blockIdx.x * blockDim.x + threadIdx.x;
    if (e < E_EDGES) {
        int d = dst[e];
        int pos = atomicAdd(&g_cursor[d], 1);
        g_sorted_src[pos] = src[e];
    }
}

// ================= mean aggregation ============================================
template <int D>
__global__ void k_aggregate(const uint8_t* __restrict__ h, uint8_t* __restrict__ agg) {
    constexpr int GRP = D / 8;
    int gthread = blockIdx.x * blockDim.x + threadIdx.x;
    int node = gthread / GRP;
    int lane = gthread % GRP;
    if (node >= N_NODES) return;
    int s0 = g_off[node], s1 = g_off[node + 1];
    size_t uoff = (size_t)(lane >> 2) * 128 + (lane & 3) * 16;
    float acc[8];
#pragma unroll
    for (int j = 0; j < 8; j++) acc[j] = 0.f;
    int e = s0;
    for (; e + 2 <= s1; e += 2) {
        int sA = g_sorted_src[e];
        int sB = g_sorted_src[e + 1];
        const uint8_t* pA = h + (size_t)sA * ROWB(D) + uoff;
        const uint8_t* pB = h + (size_t)sB * ROWB(D) + uoff;
        uint4 hiA = *(const uint4*)pA;
        uint4 loA = *(const uint4*)(pA + 64);
        uint4 hiB = *(const uint4*)pB;
        uint4 loB = *(const uint4*)(pB + 64);
        float vA[8], vB[8];
        unpack8(hiA, loA, vA);
        unpack8(hiB, loB, vB);
#pragma unroll
        for (int j = 0; j < 8; j++) acc[j] += vA[j] + vB[j];
    }
    if (e < s1) {
        int s = g_sorted_src[e];
        const uint8_t* p = h + (size_t)s * ROWB(D) + uoff;
        uint4 hi = *(const uint4*)p;
        uint4 lo = *(const uint4*)(p + 64);
        float v[8];
        unpack8(hi, lo, v);
#pragma unroll
        for (int j = 0; j < 8; j++) acc[j] += v[j];
    }
    float inv = 1.0f / fmaxf((float)(s1 - s0), 1.0f);
#pragma unroll
    for (int j = 0; j < 8; j++) acc[j] *= inv;
    uint4 hi, lo;
    split8(acc, hi, lo);
    uint8_t* o = agg + (size_t)node * ROWB(D) + uoff;
    *(uint4*)o = hi;
    *(uint4*)(o + 64) = lo;
}

// ================= GEMM building blocks ========================================
#define ASTG 16384                 // A: 128 rows x 128B per 32-k chunk
#define BSTG 32768                 // B: 256 rows x 128B per 32-k chunk
#define STAGE_B (ASTG + BSTG)      // 48KB
#define NSTAGE 3
#define GEMM_SMEM (NSTAGE * STAGE_B)       // 144KB (node GEMM)
#define FUSED_SMEM (131072 + 3 * BSTG)     // 224KB (fused predictor)

__device__ __forceinline__ void gemm_compute2(uint32_t aB, uint32_t bB, int wm, int wn,
                                              int lane, float acc[2][8][4]) {
    int mtx = lane >> 3, rin = lane & 7;
    int aRb = wm * 32 + ((mtx & 1) << 3) + rin;
    int aCb = mtx >> 1;
    int bRb = wn * 64 + ((mtx >> 1) << 3) + rin;
    int bCb = mtx & 1;
#pragma unroll
    for (int ks = 0; ks < 2; ks++) {
        uint32_t ahi[2][4], alo[2][4];
#pragma unroll
        for (int mt = 0; mt < 2; mt++) {
            int r = aRb + mt * 16;
            int ch = aCb + 2 * ks;
            ldsm4(ahi[mt], aB + r * 128 + (uint32_t)((ch ^ (r & 7)) << 4));
            ldsm4(alo[mt], aB + r * 128 + (uint32_t)(((ch + 4) ^ (r & 7)) << 4));
        }
#pragma unroll
        for (int ntp = 0; ntp < 4; ntp++) {
            int r = bRb + ntp * 16;
            int ch = bCb + 2 * ks;
            uint32_t bhi[4], blo[4];
            ldsm4(bhi, bB + r * 128 + (uint32_t)((ch ^ (r & 7)) << 4));
            ldsm4(blo, bB + r * 128 + (uint32_t)(((ch + 4) ^ (r & 7)) << 4));
#pragma unroll
            for (int mt = 0; mt < 2; mt++) {
                mma_bf16(acc[mt][2 * ntp], ahi[mt], bhi);
                mma_bf16(acc[mt][2 * ntp], alo[mt], bhi);
                mma_bf16(acc[mt][2 * ntp], ahi[mt], blo);
                mma_bf16(acc[mt][2 * ntp + 1], ahi[mt], bhi + 2);
                mma_bf16(acc[mt][2 * ntp + 1], alo[mt], bhi + 2);
                mma_bf16(acc[mt][2 * ntp + 1], ahi[mt], blo + 2);
            }
        }
    }
}

__device__ __forceinline__ void gemm_epilogue(int m0, int wm, int wn, int lane,
                                              float acc[2][8][4],
                                              const float* __restrict__ bias,
                                              uint8_t* __restrict__ out, int M, int relu) {
    int gid = lane >> 2, ctg = lane & 3;
#pragma unroll
    for (int mt = 0; mt < 2; mt++) {
        int r0 = m0 + wm * 32 + mt * 16 + gid;
#pragma unroll
        for (int nt = 0; nt < 8; nt++) {
            int col = wn * 64 + nt * 8 + ctg * 2;
            float bx = __ldg(&bias[col]), by = __ldg(&bias[col + 1]);
            size_t coff = (size_t)(col >> 5) * 128 + ((col >> 3) & 3) * 16 + (col & 7) * 2;
#pragma unroll
            for (int rr = 0; rr < 2; rr++) {
                int r = r0 + rr * 8;
                if (r >= M) continue;
                float vx = acc[mt][nt][2 * rr] + bx, vy = acc[mt][nt][2 * rr + 1] + by;
                if (relu) { vx = fmaxf(vx, 0.f); vy = fmaxf(vy, 0.f); }
                uint32_t hi, lo;
                split2(vx, vy, hi, lo);
                uint8_t* base = out + (size_t)r * ROWB(DH) + coff;
                *(uint32_t*)base = hi;
                *(uint32_t*)(base + 64) = lo;
            }
        }
    }
}

// ================= node GEMM: CTA tile 128x256, 512 thr, 3-stage ===============
__global__ __launch_bounds__(512, 1) void k_gemm_mma(
    const uint8_t* __restrict__ A1, int K1, const uint8_t* __restrict__ B1,
    const uint8_t* __restrict__ A2, int K2, const uint8_t* __restrict__ B2,
    const float* __restrict__ bias, uint8_t* __restrict__ out, int M, int relu) {
    extern __shared__ char smem[];
    int tid = threadIdx.x;
    uint32_t sbase = smem_u32(smem);
    int m0 = blockIdx.x * 128;
    int wid = tid >> 5, lane = tid & 31;
    int wm = wid >> 2, wn = wid & 3;

    int nc1 = K1 >> 5;
    int nch = nc1 + (K2 >> 5);
    int srow = tid >> 3, su = tid & 7;

    auto issue = [&](int c) {
        int stage = c % NSTAGE;
        const uint8_t* A; const uint8_t* B; int K, kc;
        if (c < nc1) { A = A1; B = B1; K = K1; kc = c; }
        else         { A = A2; B = B2; K = K2; kc = c - nc1; }
        uint32_t aB = sbase + stage * STAGE_B;
        uint32_t bB = aB + ASTG;
#pragma unroll
        for (int q = 0; q < 2; q++) {
            int row = srow + q * 64;
            uint32_t dst = aB + row * 128 + (uint32_t)((su ^ (row & 7)) << 4);
            int gr = m0 + row;
            uint32_t sz = (gr < M) ? 16u : 0u;
            const uint8_t* src = A + (size_t)(gr < M ? gr : (M - 1)) * ROWB(K) + kc * 128 + su * 16;
            cp16(dst, src, sz);
        }
#pragma unroll
        for (int q = 0; q < 4; q++) {
            int row = srow + q * 64;
            uint32_t dst = bB + row * 128 + (uint32_t)((su ^ (row & 7)) << 4);
            const uint8_t* src = B + (size_t)row * ROWB(K) + kc * 128 + su * 16;
            cp16(dst, src, 16u);
        }
        cp_commit();
    };

    issue(0);
    if (nch > 1) issue(1);

    float acc[2][8][4];
#pragma unroll
    for (int mt = 0; mt < 2; mt++)
#pragma unroll
        for (int nt = 0; nt < 8; nt++)
#pragma unroll
            for (int j = 0; j < 4; j++) acc[mt][nt][j] = 0.f;

    for (int c = 0; c < nch; c++) {
        if (c + 1 < nch) { CP_WAIT(1); } else { CP_WAIT(0); }
        __syncthreads();
        if (c + 2 < nch) issue(c + 2);
        int stage = c % NSTAGE;
        gemm_compute2(sbase + stage * STAGE_B, sbase + stage * STAGE_B + ASTG,
                      wm, wn, lane, acc);
    }
    gemm_epilogue(m0, wm, wn, lane, acc, bias, out, M, relu);
}

// ================= fused predictor: edge GEMM -> relu -> GEMM2 -> dot ==========
__global__ __launch_bounds__(512, 1) void k_pred_fused(
    const uint8_t* __restrict__ h,
    const int* __restrict__ ps, const int* __restrict__ pd,
    const int* __restrict__ ns, const int* __restrict__ nd,
    const uint8_t* __restrict__ B1, const float* __restrict__ bias1,
    const uint8_t* __restrict__ B2, const float* __restrict__ bias2,
    const float* __restrict__ wp3, const float* __restrict__ bp3,
    float* __restrict__ out) {
    extern __shared__ char smem[];
    int tid = threadIdx.x;
    uint32_t sbase = smem_u32(smem);
    int m0 = blockIdx.x * 128;
    int wid = tid >> 5, lane = tid & 31;
    int wm = wid >> 2, wn = wid & 3;
    int gid = lane >> 2, ctg = lane & 3;

    const int nch = DH >> 5;  // 8
    int srow = tid >> 3, su = tid & 7;

    // -------- phase 1: z = relu(h[s]*h[d] @ Wp1 + b1), kept in smem ------------
    int r = tid >> 2, q4 = tid & 3;
    int gr = m0 + r;
    bool valid = gr < M_PRED;
    int s = 0, d = 0;
    if (valid) {
        if (gr < P_PAIRS) { s = ps[gr]; d = pd[gr]; }
        else              { s = ns[gr - P_PAIRS]; d = nd[gr - P_PAIRS]; }
    }
    const uint8_t* rowS = h + (size_t)s * ROWB(DH);
    const uint8_t* rowD = h + (size_t)d * ROWB(DH);

    auto stage_a = [&](int c) {
        int stage = c % NSTAGE;
        uint32_t aB = sbase + stage * STAGE_B;
        int ch = q4;
        float v[8];
        if (valid) {
            const uint8_t* pS = rowS + c * 128 + ch * 16;
            const uint8_t* pD = rowD + c * 128 + ch * 16;
            uint4 shi = *(const uint4*)pS, slo = *(const uint4*)(pS + 64);
            uint4 dhi = *(const uint4*)pD, dlo = *(const uint4*)(pD + 64);
            float sv[8], dv[8];
            unpack8(shi, slo, sv);
            unpack8(dhi, dlo, dv);
#pragma unroll
            for (int j = 0; j < 8; j++) v[j] = sv[j] * dv[j];
        } else {
#pragma unroll
            for (int j = 0; j < 8; j++) v[j] = 0.f;
        }
        uint4 hi, lo;
        split8(v, hi, lo);
        uint32_t dhiA = aB + r * 128 + (uint32_t)((ch ^ (r & 7)) << 4);
        uint32_t dloA = aB + r * 128 + (uint32_t)(((ch + 4) ^ (r & 7)) << 4);
        asm volatile("st.shared.v4.b32 [%0], {%1,%2,%3,%4};"
                     :: "r"(dhiA), "r"(hi.x), "r"(hi.y), "r"(hi.z), "r"(hi.w) : "memory");
        asm volatile("st.shared.v4.b32 [%0], {%1,%2,%3,%4};"
                     :: "r"(dloA), "r"(lo.x), "r"(lo.y), "r"(lo.z), "r"(lo.w) : "memory");
    };
    auto issue_b1 = [&](int c) {
        int stage = c % NSTAGE;
        uint32_t bB = sbase + stage * STAGE_B + ASTG;
#pragma unroll
        for (int q = 0; q < 4; q++) {
            int row = srow + q * 64;
            uint32_t dst = bB + row * 128 + (uint32_t)((su ^ (row & 7)) << 4);
            const uint8_t* src = B1 + (size_t)row * ROWB(DH) + c * 128 + su * 16;
            cp16(dst, src, 16u);
        }
        cp_commit();
    };

    stage_a(0); issue_b1(0);
    stage_a(1); issue_b1(1);

    float acc[2][8][4];
#pragma unroll
    for (int mt = 0; mt < 2; mt++)
#pragma unroll
        for (int nt = 0; nt < 8; nt++)
#pragma unroll
            for (int j = 0; j < 4; j++) acc[mt][nt][j] = 0.f;

    for (int c = 0; c < nch; c++) {
        if (c + 1 < nch) { CP_WAIT(1); } else { CP_WAIT(0); }
        __syncthreads();
        if (c + 2 < nch) { stage_a(c + 2); issue_b1(c + 2); }
        int stage = c % NSTAGE;
        gemm_compute2(sbase + stage * STAGE_B, sbase + stage * STAGE_B + ASTG,
                      wm, wn, lane, acc);
    }

    // -------- inter-phase: write relu(acc + b1) as split-bf16 into smem A ------
    __syncthreads();   // all phase-1 ldsm done; safe to overwrite stage memory
#pragma unroll
    for (int mt = 0; mt < 2; mt++) {
#pragma unroll
        for (int nt = 0; nt < 8; nt++) {
            int col = wn * 64 + nt * 8 + ctg * 2;
            float bx = __ldg(&bias1[col]), by = __ldg(&bias1[col + 1]);
            int blk = col >> 5, ch = (col >> 3) & 3, within = (col & 7) * 2;
#pragma unroll
            for (int rr = 0; rr < 2; rr++) {
                int rl = wm * 32 + mt * 16 + rr * 8 + gid;   // local row 0..127
                float vx = fmaxf(acc[mt][nt][2 * rr] + bx, 0.f);
                float vy = fmaxf(acc[mt][nt][2 * rr + 1] + by, 0.f);
                uint32_t hi, lo;
                split2(vx, vy, hi, lo);
                uint32_t base = sbase + blk * ASTG + rl * 128;
                uint32_t ahiA = base + (uint32_t)((ch ^ (rl & 7)) << 4) + within;
                uint32_t aloA = base + (uint32_t)(((ch + 4) ^ (rl & 7)) << 4) + within;
                asm volatile("st.shared.b32 [%0], %1;" :: "r"(ahiA), "r"(hi) : "memory");
                asm volatile("st.shared.b32 [%0], %1;" :: "r"(aloA), "r"(lo) : "memory");
            }
        }
    }
    __syncthreads();

    // -------- phase 2: acc2 = z @ Wp2 ; out = relu(acc2+b2) . wp3 + bp3 --------
    uint32_t b2base = sbase + 131072;   // 3-stage ring of 32KB
    auto issue_b2 = [&](int c) {
        int stage = c % NSTAGE;
        uint32_t bB = b2base + stage * BSTG;
#pragma unroll
        for (int q = 0; q < 4; q++) {
            int row = srow + q * 64;
            uint32_t dst = bB + row * 128 + (uint32_t)((su ^ (row & 7)) << 4);
            const uint8_t* src = B2 + (size_t)row * ROWB(DH) + c * 128 + su * 16;
            cp16(dst, src, 16u);
        }
        cp_commit();
    };

    issue_b2(0);
    issue_b2(1);

#pragma unroll
    for (int mt = 0; mt < 2; mt++)
#pragma unroll
        for (int nt = 0; nt < 8; nt++)
#pragma unroll
            for (int j = 0; j < 4; j++) acc[mt][nt][j] = 0.f;

    for (int c = 0; c < nch; c++) {
        if (c + 1 < nch) { CP_WAIT(1); } else { CP_WAIT(0); }
        __syncthreads();
        if (c + 2 < nch) issue_b2(c + 2);
        gemm_compute2(sbase + c * ASTG, b2base + (c % NSTAGE) * BSTG, wm, wn, lane, acc);
    }

    // per-row reduction across the 4 wn warp-columns via smem atomics
    __syncthreads();
    float* buf = (float*)smem;   // reuse A chunk-0 region (128 floats)
    if (tid < 128) buf[tid] = 0.f;
    __syncthreads();
#pragma unroll
    for (int mt = 0; mt < 2; mt++) {
#pragma unroll
        for (int rr = 0; rr < 2; rr++) {
            int rl = wm * 32 + mt * 16 + rr * 8 + gid;
            float p = 0.f;
#pragma unroll
            for (int nt = 0; nt < 8; nt++) {
                int col = wn * 64 + nt * 8 + ctg * 2;
                float vx = fmaxf(acc[mt][nt][2 * rr] + __ldg(&bias2[col]), 0.f);
                float vy = fmaxf(acc[mt][nt][2 * rr + 1] + __ldg(&bias2[col + 1]), 0.f);
                p += vx * __ldg(&wp3[col]) + vy * __ldg(&wp3[col + 1]);
            }
            p += __shfl_xor_sync(0xFFFFFFFFu, p, 1);
            p += __shfl_xor_sync(0xFFFFFFFFu, p, 2);
            if (ctg == 0) atomicAdd(&buf[rl], p);
        }
    }
    __syncthreads();
    if (tid < 128 && m0 + tid < M_PRED) out[m0 + tid] = buf[tid] + __ldg(&bp3[0]);
}

// ================= host orchestration ==========================================
extern "C" void kernel_launch(void* const* d_in, const int* in_sizes, int n_in,
                              void* d_out, int out_size) {
    const float* x        = (const float*)d_in[0];
    const int*   edge_src = (const int*)d_in[1];
    const int*   edge_dst = (const int*)d_in[2];
    const int*   pos_src  = (const int*)d_in[3];
    const int*   pos_dst  = (const int*)d_in[4];
    const int*   neg_src  = (const int*)d_in[5];
    const int*   neg_dst  = (const int*)d_in[6];
    const float* Ws0 = (const float*)d_in[7];
    const float* Wn0 = (const float*)d_in[8];
    const float* b0  = (const float*)d_in[9];
    const float* Ws1 = (const float*)d_in[10];
    const float* Wn1 = (const float*)d_in[11];
    const float* b1  = (const float*)d_in[12];
    const float* Ws2 = (const float*)d_in[13];
    const float* Wn2 = (const float*)d_in[14];
    const float* b2  = (const float*)d_in[15];
    const float* Wp1 = (const float*)d_in[16];
    const float* bp1 = (const float*)d_in[17];
    const float* Wp2 = (const float*)d_in[18];
    const float* bp2 = (const float*)d_in[19];
    const float* Wp3 = (const float*)d_in[20];
    const float* bp3 = (const float*)d_in[21];
    float* out = (float*)d_out;

    uint8_t *xs, *agg, *h1, *h2, *h3, *wt;
    cudaGetSymbolAddress((void**)&xs, g_xs);
    cudaGetSymbolAddress((void**)&agg, g_agg);
    cudaGetSymbolAddress((void**)&h1, g_h1);
    cudaGetSymbolAddress((void**)&h2, g_h2);
    cudaGetSymbolAddress((void**)&h3, g_h3);
    cudaGetSymbolAddress((void**)&wt, g_wt);

    cudaFuncSetAttribute(k_gemm_mma, cudaFuncAttributeMaxDynamicSharedMemorySize, GEMM_SMEM);
    cudaFuncSetAttribute(k_pred_fused, cudaFuncAttributeMaxDynamicSharedMemorySize, FUSED_SMEM);

    const int AGG_BLOCKS_DIN = (N_NODES * 16 + 255) / 256;
    const int AGG_BLOCKS_DH  = (N_NODES * 32 + 255) / 256;
    const int NODE_TILES = (N_NODES + 127) / 128;   // 391
    const int PRED_TILES = (M_PRED + 127) / 128;    // 1563

    PrepWAll pw;
    pw.src[0] = Ws0; pw.dst[0] = wt + WT_WS0; pw.K[0] = DIN;
    pw.src[1] = Wn0; pw.dst[1] = wt + WT_WN0; pw.K[1] = DIN;
    pw.src[2] = Ws1; pw.dst[2] = wt + WT_WS1; pw.K[2] = DH;
    pw.src[3] = Wn1; pw.dst[3] = wt + WT_WN1; pw.K[3] = DH;
    pw.src[4] = Ws2; pw.dst[4] = wt + WT_WS2; pw.K[4] = DH;
    pw.src[5] = Wn2; pw.dst[5] = wt + WT_WN2; pw.K[5] = DH;
    pw.src[6] = Wp1; pw.dst[6] = wt + WT_WP1; pw.K[6] = DH;
    pw.src[7] = Wp2; pw.dst[7] = wt + WT_WP2; pw.K[7] = DH;

    // merged prep (x split + zero deg + weight prep), then CSR
    k_prep_all<<<PREP0_BLOCKS + PREPW_BLOCKS, 256>>>(x, xs, pw);
    k_count<<<(E_EDGES + 255) / 256, 256>>>(edge_dst);
    k_scan_block<<<(N_NODES + 1023) / 1024, 1024>>>();
    k_scan_add2<<<(N_NODES + 255) / 256, 256>>>();
    k_scatter<<<(E_EDGES + 255) / 256, 256>>>(edge_src, edge_dst);

    // Layer 0
    k_aggregate<DIN><<<AGG_BLOCKS_DIN, 256>>>(xs, agg);
    k_gemm_mma<<<NODE_TILES, 512, GEMM_SMEM>>>(xs, DIN, wt + WT_WS0, agg, DIN, wt + WT_WN0,
                                               b0, h1, N_NODES, 1);
    // Layer 1
    k_aggregate<DH><<<AGG_BLOCKS_DH, 256>>>(h1, agg);
    k_gemm_mma<<<NODE_TILES, 512, GEMM_SMEM>>>(h1, DH, wt + WT_WS1, agg, DH, wt + WT_WN1,
                                               b1, h2, N_NODES, 1);
    // Layer 2 (no relu)
    k_aggregate<DH><<<AGG_BLOCKS_DH, 256>>>(h2, agg);
    k_gemm_mma<<<NODE_TILES, 512, GEMM_SMEM>>>(h2, DH, wt + WT_WS2, agg, DH, wt + WT_WN2,
                                               b2, h3, N_NODES, 0);

    // Fused predictor (edge GEMM -> relu -> GEMM2 -> final dot)
    k_pred_fused<<<PRED_TILES, 512, FUSED_SMEM>>>(h3, pos_src, pos_dst, neg_src, neg_dst,
                                                  wt + WT_WP1, bp1, wt + WT_WP2, bp2,
                                                  Wp3, bp3, out);
}

// round 15
// speedup vs baseline: 1.0080x; 1.0080x over previous
#include <cuda_runtime.h>
#include <cuda_bf16.h>
#include <cstdint>

#define N_NODES 50000
#define E_EDGES 800000
#define DIN 128
#define DH 256
#define P_PAIRS 100000
#define M_PRED (2 * P_PAIRS)

// ================= helpers =====================================================
__device__ __forceinline__ uint32_t smem_u32(const void* p) {
    uint32_t a;
    asm("{ .reg .u64 t; cvta.to.shared.u64 t, %1; cvt.u32.u64 %0, t; }" : "=r"(a) : "l"(p));
    return a;
}
__device__ __forceinline__ void cp16(uint32_t dst, const void* src, uint32_t sz) {
    asm volatile("cp.async.cg.shared.global [%0], [%1], 16, %2;"
                 :: "r"(dst), "l"(src), "r"(sz) : "memory");
}
__device__ __forceinline__ void cp_commit() {
    asm volatile("cp.async.commit_group;" ::: "memory");
}
#define CP_WAIT(n) asm volatile("cp.async.wait_group %0;" :: "n"(n) : "memory")

__device__ __forceinline__ void ldsm4(uint32_t* r, uint32_t addr) {
    asm volatile("ldmatrix.sync.aligned.m8n8.x4.shared.b16 {%0,%1,%2,%3}, [%4];"
                 : "=r"(r[0]), "=r"(r[1]), "=r"(r[2]), "=r"(r[3]) : "r"(addr));
}
__device__ __forceinline__ void mma_bf16(float* d, const uint32_t* a, const uint32_t* b) {
    asm volatile(
        "mma.sync.aligned.m16n8k16.row.col.f32.bf16.bf16.f32 "
        "{%0,%1,%2,%3}, {%4,%5,%6,%7}, {%8,%9}, {%0,%1,%2,%3};"
        : "+f"(d[0]), "+f"(d[1]), "+f"(d[2]), "+f"(d[3])
        : "r"(a[0]), "r"(a[1]), "r"(a[2]), "r"(a[3]), "r"(b[0]), "r"(b[1]));
}

// split fp32 -> (hi, lo) bf16
__device__ __forceinline__ void split1(float v, uint16_t& h, uint16_t& l) {
    __nv_bfloat16 hb = __float2bfloat16_rn(v);
    float r = v - __bfloat162float(hb);
    __nv_bfloat16 lb = __float2bfloat16_rn(r);
    h = __bfloat16_as_ushort(hb);
    l = __bfloat16_as_ushort(lb);
}
__device__ __forceinline__ void split2(float v0, float v1, uint32_t& hi, uint32_t& lo) {
    uint16_t h0, l0, h1, l1;
    split1(v0, h0, l0); split1(v1, h1, l1);
    hi = (uint32_t)h0 | ((uint32_t)h1 << 16);
    lo = (uint32_t)l0 | ((uint32_t)l1 << 16);
}
__device__ __forceinline__ void split8(const float* v, uint4& hi, uint4& lo) {
    uint32_t h[4], l[4];
#pragma unroll
    for (int i = 0; i < 4; i++) split2(v[2 * i], v[2 * i + 1], h[i], l[i]);
    hi = make_uint4(h[0], h[1], h[2], h[3]);
    lo = make_uint4(l[0], l[1], l[2], l[3]);
}
__device__ __forceinline__ void unpack8(uint4 hi, uint4 lo, float* v) {
    uint32_t hw[4] = {hi.x, hi.y, hi.z, hi.w};
    uint32_t lw[4] = {lo.x, lo.y, lo.z, lo.w};
#pragma unroll
    for (int i = 0; i < 4; i++) {
        v[2 * i]     = __uint_as_float(hw[i] << 16) + __uint_as_float(lw[i] << 16);
        v[2 * i + 1] = __uint_as_float(hw[i] & 0xffff0000u) + __uint_as_float(lw[i] & 0xffff0000u);
    }
}

// Split tensor layout: row r of a [M, K] tensor occupies K*4 bytes:
//   (K/32) blocks of 128B; block = [4 x 16B hi chunks (k=0..31) | 4 x 16B lo chunks]
#define ROWB(K) ((K) * 4)

// ================= scratch =====================================================
__device__ int g_deg[N_NODES];
__device__ int g_off[N_NODES + 1];
__device__ int g_cursor[N_NODES];
__device__ int g_sorted_src[E_EDGES];
__device__ int g_bsum[64];
__device__ __align__(16) uint8_t g_xs[(size_t)N_NODES * DIN * 4];
__device__ __align__(16) uint8_t g_agg[(size_t)N_NODES * DH * 4];
__device__ __align__(16) uint8_t g_h1[(size_t)N_NODES * DH * 4];
__device__ __align__(16) uint8_t g_h2[(size_t)N_NODES * DH * 4];
__device__ __align__(16) uint8_t g_h3[(size_t)N_NODES * DH * 4];
__device__ __align__(16) uint8_t g_wt[1835008];

#define WT_WS0 0
#define WT_WN0 131072
#define WT_WS1 262144
#define WT_WN1 524288
#define WT_WS2 786432
#define WT_WN2 1048576
#define WT_WP1 1310720
#define WT_WP2 1572864

// ================= merged prep: split x + prep W + count deg ===================
struct PrepWAll {
    const float* src[8];
    uint8_t* dst[8];
    int K[8];
};

#define PREP0_BLOCKS 3125          // (N_NODES * 16) / 256
#define PREPW_BLOCKS 256
#define COUNT_BLOCKS 3125          // ceil(E_EDGES / 256)

__global__ void k_prep_all(const float* __restrict__ x, uint8_t* __restrict__ xs,
                           PrepWAll a, const int* __restrict__ edge_dst) {
    int b = blockIdx.x;
    int t = threadIdx.x;
    if (b < PREP0_BLOCKS) {
        int i = b * 256 + t;
        const int units = DIN >> 3;
        if (i < N_NODES * units) {
            int row = i / units, u = i % units;
            const float* src = x + (size_t)row * DIN + u * 8;
            float v[8];
#pragma unroll
            for (int j = 0; j < 8; j++) v[j] = src[j];
            uint4 hi, lo;
            split8(v, hi, lo);
            uint8_t* base = xs + (size_t)row * ROWB(DIN) + (u >> 2) * 128 + (u & 3) * 16;
            *(uint4*)base = hi;
            *(uint4*)(base + 64) = lo;
        }
        return;
    }
    b -= PREP0_BLOCKS;
    if (b < PREPW_BLOCKS) {
        int w = b >> 5;
        int k0 = ((b >> 2) & 7) * 32;
        int n0 = (b & 3) * 64;
        int K = a.K[w];
        if (k0 >= K) return;
        const float* src = a.src[w];
        uint8_t* dst = a.dst[w];
        __shared__ float s[32][65];
#pragma unroll
        for (int l = 0; l < 8; l++) {
            int idx = t + 256 * l;
            int i = idx >> 6, j = idx & 63;
            s[i][j] = src[(size_t)(k0 + i) * DH + n0 + j];
        }
        __syncthreads();
        int n = t >> 2, kc = t & 3;
        float v[8];
#pragma unroll
        for (int q = 0; q < 8; q++) v[q] = s[kc * 8 + q][n];
        uint4 hi, lo;
        split8(v, hi, lo);
        int k = k0 + kc * 8;
        uint8_t* base = dst + (size_t)(n0 + n) * ROWB(K) + (k >> 5) * 128 + ((k >> 3) & 3) * 16;
        *(uint4*)base = hi;
        *(uint4*)(base + 64) = lo;
        return;
    }
    b -= PREPW_BLOCKS;
    {
        int e = b * 256 + t;
        if (e < E_EDGES) atomicAdd(&g_deg[edge_dst[e]], 1);
    }
}

// ================= CSR build ===================================================
__global__ void k_scan_block() {
    __shared__ int s[1024];
    int i = blockIdx.x * 1024 + threadIdx.x;
    int v = (i < N_NODES) ? g_deg[i] : 0;
    s[threadIdx.x] = v;
    __syncthreads();
    for (int ofs = 1; ofs < 1024; ofs <<= 1) {
        int t = (threadIdx.x >= ofs) ? s[threadIdx.x - ofs] : 0;
        __syncthreads();
        s[threadIdx.x] += t;
        __syncthreads();
    }
    if (i < N_NODES) g_off[i] = s[threadIdx.x] - v;
    if (threadIdx.x == 1023) g_bsum[blockIdx.x] = s[1023];
}
__global__ void k_scan_add2() {
    __shared__ int sb[64];
    int tid = threadIdx.x;
    const int nb = (N_NODES + 1023) >> 10;
    if (tid < 64) sb[tid] = (tid < nb) ? g_bsum[tid] : 0;
    __syncthreads();
    for (int ofs = 1; ofs < 64; ofs <<= 1) {
        int t = 0;
        if (tid < 64 && tid >= ofs) t = sb[tid - ofs];
        __syncthreads();
        if (tid < 64) sb[tid] += t;
        __syncthreads();
    }
    int i = blockIdx.x * blockDim.x + tid;
    if (i < N_NODES) {
        int blk = i >> 10;
        int base = blk ? sb[blk - 1] : 0;
        int o = g_off[i] + base;
        g_off[i] = o;
        g_cursor[i] = o;
    }
    if (i == 0) g_off[N_NODES] = E_EDGES;
}
__global__ void k_scatter(const int* __restrict__ src, const int* __restrict__ dst) {
    int e = blockIdx.x * blockDim.x + threadIdx.x;
    if (e < E_EDGES) {
        int d = dst[e];
        int pos = atomicAdd(&g_cursor[d], 1);
        g_sorted_src[pos] = src[e];
    }
}

// ================= mean aggregation (edge loop unrolled x2) ====================
template <int D>
__global__ void k_aggregate(const uint8_t* __restrict__ h, uint8_t* __restrict__ agg) {
    constexpr int GRP = D / 8;
    int gthread = blockIdx.x * blockDim.x + threadIdx.x;
    int node = gthread / GRP;
    int lane = gthread % GRP;
    if (node >= N_NODES) return;
    int s0 = g_off[node], s1 = g_off[node + 1];
    size_t uoff = (size_t)(lane >> 2) * 128 + (lane & 3) * 16;
    float acc[8];
#pragma unroll
    for (int j = 0; j < 8; j++) acc[j] = 0.f;
    int e = s0;
    for (; e + 2 <= s1; e += 2) {
        int sA = g_sorted_src[e];
        int sB = g_sorted_src[e + 1];
        const uint8_t* pA = h + (size_t)sA * ROWB(D) + uoff;
        const uint8_t* pB = h + (size_t)sB * ROWB(D) + uoff;
        uint4 hiA = *(const uint4*)pA;
        uint4 loA = *(const uint4*)(pA + 64);
        uint4 hiB = *(const uint4*)pB;
        uint4 loB = *(const uint4*)(pB + 64);
        float vA[8], vB[8];
        unpack8(hiA, loA, vA);
        unpack8(hiB, loB, vB);
#pragma unroll
        for (int j = 0; j < 8; j++) acc[j] += vA[j] + vB[j];
    }
    if (e < s1) {
        int s = g_sorted_src[e];
        const uint8_t* p = h + (size_t)s * ROWB(D) + uoff;
        uint4 hi = *(const uint4*)p;
        uint4 lo = *(const uint4*)(p + 64);
        float v[8];
        unpack8(hi, lo, v);
#pragma unroll
        for (int j = 0; j < 8; j++) acc[j] += v[j];
    }
    float inv = 1.0f / fmaxf((float)(s1 - s0), 1.0f);
#pragma unroll
    for (int j = 0; j < 8; j++) acc[j] *= inv;
    uint4 hi, lo;
    split8(acc, hi, lo);
    uint8_t* o = agg + (size_t)node * ROWB(D) + uoff;
    *(uint4*)o = hi;
    *(uint4*)(o + 64) = lo;
}

// ================= GEMM building blocks ========================================
#define ASTG 16384                 // A: 128 rows x 128B per 32-k chunk
#define BSTG 32768                 // B: 256 rows x 128B per 32-k chunk
#define STAGE_B (ASTG + BSTG)      // 48KB
#define NSTAGE 3
#define GEMM_SMEM (NSTAGE * STAGE_B)       // 144KB (node GEMM)
#define FUSED_SMEM (131072 + 3 * BSTG)     // 224KB (fused predictor)

__device__ __forceinline__ void gemm_compute2(uint32_t aB, uint32_t bB, int wm, int wn,
                                              int lane, float acc[2][8][4]) {
    int mtx = lane >> 3, rin = lane & 7;
    int aRb = wm * 32 + ((mtx & 1) << 3) + rin;
    int aCb = mtx >> 1;
    int bRb = wn * 64 + ((mtx >> 1) << 3) + rin;
    int bCb = mtx & 1;
#pragma unroll
    for (int ks = 0; ks < 2; ks++) {
        uint32_t ahi[2][4], alo[2][4];
#pragma unroll
        for (int mt = 0; mt < 2; mt++) {
            int r = aRb + mt * 16;
            int ch = aCb + 2 * ks;
            ldsm4(ahi[mt], aB + r * 128 + (uint32_t)((ch ^ (r & 7)) << 4));
            ldsm4(alo[mt], aB + r * 128 + (uint32_t)(((ch + 4) ^ (r & 7)) << 4));
        }
#pragma unroll
        for (int ntp = 0; ntp < 4; ntp++) {
            int r = bRb + ntp * 16;
            int ch = bCb + 2 * ks;
            uint32_t bhi[4], blo[4];
            ldsm4(bhi, bB + r * 128 + (uint32_t)((ch ^ (r & 7)) << 4));
            ldsm4(blo, bB + r * 128 + (uint32_t)(((ch + 4) ^ (r & 7)) << 4));
#pragma unroll
            for (int mt = 0; mt < 2; mt++) {
                mma_bf16(acc[mt][2 * ntp], ahi[mt], bhi);
                mma_bf16(acc[mt][2 * ntp], alo[mt], bhi);
                mma_bf16(acc[mt][2 * ntp], ahi[mt], blo);
                mma_bf16(acc[mt][2 * ntp + 1], ahi[mt], bhi + 2);
                mma_bf16(acc[mt][2 * ntp + 1], alo[mt], bhi + 2);
                mma_bf16(acc[mt][2 * ntp + 1], ahi[mt], blo + 2);
            }
        }
    }
}

__device__ __forceinline__ void gemm_epilogue(int m0, int wm, int wn, int lane,
                                              float acc[2][8][4],
                                              const float* __restrict__ bias,
                                              uint8_t* __restrict__ out, int M, int relu) {
    int gid = lane >> 2, ctg = lane & 3;
#pragma unroll
    for (int mt = 0; mt < 2; mt++) {
        int r0 = m0 + wm * 32 + mt * 16 + gid;
#pragma unroll
        for (int nt = 0; nt < 8; nt++) {
            int col = wn * 64 + nt * 8 + ctg * 2;
            float bx = __ldg(&bias[col]), by = __ldg(&bias[col + 1]);
            size_t coff = (size_t)(col >> 5) * 128 + ((col >> 3) & 3) * 16 + (col & 7) * 2;
#pragma unroll
            for (int rr = 0; rr < 2; rr++) {
                int r = r0 + rr * 8;
                if (r >= M) continue;
                float vx = acc[mt][nt][2 * rr] + bx, vy = acc[mt][nt][2 * rr + 1] + by;
                if (relu) { vx = fmaxf(vx, 0.f); vy = fmaxf(vy, 0.f); }
                uint32_t hi, lo;
                split2(vx, vy, hi, lo);
                uint8_t* base = out + (size_t)r * ROWB(DH) + coff;
                *(uint32_t*)base = hi;
                *(uint32_t*)(base + 64) = lo;
            }
        }
    }
}

// ================= node GEMM: CTA tile 128x256, 512 thr, 3-stage ===============
__global__ __launch_bounds__(512, 1) void k_gemm_mma(
    const uint8_t* __restrict__ A1, int K1, const uint8_t* __restrict__ B1,
    const uint8_t* __restrict__ A2, int K2, const uint8_t* __restrict__ B2,
    const float* __restrict__ bias, uint8_t* __restrict__ out, int M, int relu) {
    extern __shared__ char smem[];
    int tid = threadIdx.x;
    uint32_t sbase = smem_u32(smem);
    int m0 = blockIdx.x * 128;
    int wid = tid >> 5, lane = tid & 31;
    int wm = wid >> 2, wn = wid & 3;

    int nc1 = K1 >> 5;
    int nch = nc1 + (K2 >> 5);
    int srow = tid >> 3, su = tid & 7;

    auto issue = [&](int c) {
        int stage = c % NSTAGE;
        const uint8_t* A; const uint8_t* B; int K, kc;
        if (c < nc1) { A = A1; B = B1; K = K1; kc = c; }
        else         { A = A2; B = B2; K = K2; kc = c - nc1; }
        uint32_t aB = sbase + stage * STAGE_B;
        uint32_t bB = aB + ASTG;
#pragma unroll
        for (int q = 0; q < 2; q++) {
            int row = srow + q * 64;
            uint32_t dst = aB + row * 128 + (uint32_t)((su ^ (row & 7)) << 4);
            int gr = m0 + row;
            uint32_t sz = (gr < M) ? 16u : 0u;
            const uint8_t* src = A + (size_t)(gr < M ? gr : (M - 1)) * ROWB(K) + kc * 128 + su * 16;
            cp16(dst, src, sz);
        }
#pragma unroll
        for (int q = 0; q < 4; q++) {
            int row = srow + q * 64;
            uint32_t dst = bB + row * 128 + (uint32_t)((su ^ (row & 7)) << 4);
            const uint8_t* src = B + (size_t)row * ROWB(K) + kc * 128 + su * 16;
            cp16(dst, src, 16u);
        }
        cp_commit();
    };

    issue(0);
    if (nch > 1) issue(1);

    float acc[2][8][4];
#pragma unroll
    for (int mt = 0; mt < 2; mt++)
#pragma unroll
        for (int nt = 0; nt < 8; nt++)
#pragma unroll
            for (int j = 0; j < 4; j++) acc[mt][nt][j] = 0.f;

    for (int c = 0; c < nch; c++) {
        if (c + 1 < nch) { CP_WAIT(1); } else { CP_WAIT(0); }
        __syncthreads();
        if (c + 2 < nch) issue(c + 2);
        int stage = c % NSTAGE;
        gemm_compute2(sbase + stage * STAGE_B, sbase + stage * STAGE_B + ASTG,
                      wm, wn, lane, acc);
    }
    gemm_epilogue(m0, wm, wn, lane, acc, bias, out, M, relu);
}

// ================= fused predictor: edge GEMM -> relu -> GEMM2 -> dot ==========
__global__ __launch_bounds__(512, 1) void k_pred_fused(
    const uint8_t* __restrict__ h,
    const int* __restrict__ ps, const int* __restrict__ pd,
    const int* __restrict__ ns, const int* __restrict__ nd,
    const uint8_t* __restrict__ B1, const float* __restrict__ bias1,
    const uint8_t* __restrict__ B2, const float* __restrict__ bias2,
    const float* __restrict__ wp3, const float* __restrict__ bp3,
    float* __restrict__ out) {
    extern __shared__ char smem[];
    int tid = threadIdx.x;
    uint32_t sbase = smem_u32(smem);
    int m0 = blockIdx.x * 128;
    int wid = tid >> 5, lane = tid & 31;
    int wm = wid >> 2, wn = wid & 3;
    int gid = lane >> 2, ctg = lane & 3;

    const int nch = DH >> 5;  // 8
    int srow = tid >> 3, su = tid & 7;

    // -------- phase 1: z = relu(h[s]*h[d] @ Wp1 + b1), kept in smem ------------
    int r = tid >> 2, q4 = tid & 3;
    int gr = m0 + r;
    bool valid = gr < M_PRED;
    int s = 0, d = 0;
    if (valid) {
        if (gr < P_PAIRS) { s = ps[gr]; d = pd[gr]; }
        else              { s = ns[gr - P_PAIRS]; d = nd[gr - P_PAIRS]; }
    }
    const uint8_t* rowS = h + (size_t)s * ROWB(DH);
    const uint8_t* rowD = h + (size_t)d * ROWB(DH);

    auto stage_a = [&](int c) {
        int stage = c % NSTAGE;
        uint32_t aB = sbase + stage * STAGE_B;
        int ch = q4;
        float v[8];
        if (valid) {
            const uint8_t* pS = rowS + c * 128 + ch * 16;
            const uint8_t* pD = rowD + c * 128 + ch * 16;
            uint4 shi = *(const uint4*)pS, slo = *(const uint4*)(pS + 64);
            uint4 dhi = *(const uint4*)pD, dlo = *(const uint4*)(pD + 64);
            float sv[8], dv[8];
            unpack8(shi, slo, sv);
            unpack8(dhi, dlo, dv);
#pragma unroll
            for (int j = 0; j < 8; j++) v[j] = sv[j] * dv[j];
        } else {
#pragma unroll
            for (int j = 0; j < 8; j++) v[j] = 0.f;
        }
        uint4 hi, lo;
        split8(v, hi, lo);
        uint32_t dhiA = aB + r * 128 + (uint32_t)((ch ^ (r & 7)) << 4);
        uint32_t dloA = aB + r * 128 + (uint32_t)(((ch + 4) ^ (r & 7)) << 4);
        asm volatile("st.shared.v4.b32 [%0], {%1,%2,%3,%4};"
                     :: "r"(dhiA), "r"(hi.x), "r"(hi.y), "r"(hi.z), "r"(hi.w) : "memory");
        asm volatile("st.shared.v4.b32 [%0], {%1,%2,%3,%4};"
                     :: "r"(dloA), "r"(lo.x), "r"(lo.y), "r"(lo.z), "r"(lo.w) : "memory");
    };
    auto issue_b1 = [&](int c) {
        int stage = c % NSTAGE;
        uint32_t bB = sbase + stage * STAGE_B + ASTG;
#pragma unroll
        for (int q = 0; q < 4; q++) {
            int row = srow + q * 64;
            uint32_t dst = bB + row * 128 + (uint32_t)((su ^ (row & 7)) << 4);
            const uint8_t* src = B1 + (size_t)row * ROWB(DH) + c * 128 + su * 16;
            cp16(dst, src, 16u);
        }
        cp_commit();
    };

    stage_a(0); issue_b1(0);
    stage_a(1); issue_b1(1);

    float acc[2][8][4];
#pragma unroll
    for (int mt = 0; mt < 2; mt++)
#pragma unroll
        for (int nt = 0; nt < 8; nt++)
#pragma unroll
            for (int j = 0; j < 4; j++) acc[mt][nt][j] = 0.f;

    for (int c = 0; c < nch; c++) {
        if (c + 1 < nch) { CP_WAIT(1); } else { CP_WAIT(0); }
        __syncthreads();
        if (c + 2 < nch) { stage_a(c + 2); issue_b1(c + 2); }
        int stage = c % NSTAGE;
        gemm_compute2(sbase + stage * STAGE_B, sbase + stage * STAGE_B + ASTG,
                      wm, wn, lane, acc);
    }

    // -------- inter-phase: write relu(acc + b1) as split-bf16 into smem A ------
    __syncthreads();
#pragma unroll
    for (int mt = 0; mt < 2; mt++) {
#pragma unroll
        for (int nt = 0; nt < 8; nt++) {
            int col = wn * 64 + nt * 8 + ctg * 2;
            float bx = __ldg(&bias1[col]), by = __ldg(&bias1[col + 1]);
            int blk = col >> 5, ch = (col >> 3) & 3, within = (col & 7) * 2;
#pragma unroll
            for (int rr = 0; rr < 2; rr++) {
                int rl = wm * 32 + mt * 16 + rr * 8 + gid;
                float vx = fmaxf(acc[mt][nt][2 * rr] + bx, 0.f);
                float vy = fmaxf(acc[mt][nt][2 * rr + 1] + by, 0.f);
                uint32_t hi, lo;
                split2(vx, vy, hi, lo);
                uint32_t base = sbase + blk * ASTG + rl * 128;
                uint32_t ahiA = base + (uint32_t)((ch ^ (rl & 7)) << 4) + within;
                uint32_t aloA = base + (uint32_t)(((ch + 4) ^ (rl & 7)) << 4) + within;
                asm volatile("st.shared.b32 [%0], %1;" :: "r"(ahiA), "r"(hi) : "memory");
                asm volatile("st.shared.b32 [%0], %1;" :: "r"(aloA), "r"(lo) : "memory");
            }
        }
    }
    __syncthreads();

    // -------- phase 2: acc2 = z @ Wp2 ; out = relu(acc2+b2) . wp3 + bp3 --------
    uint32_t b2base = sbase + 131072;
    auto issue_b2 = [&](int c) {
        int stage = c % NSTAGE;
        uint32_t bB = b2base + stage * BSTG;
#pragma unroll
        for (int q = 0; q < 4; q++) {
            int row = srow + q * 64;
            uint32_t dst = bB + row * 128 + (uint32_t)((su ^ (row & 7)) << 4);
            const uint8_t* src = B2 + (size_t)row * ROWB(DH) + c * 128 + su * 16;
            cp16(dst, src, 16u);
        }
        cp_commit();
    };

    issue_b2(0);
    issue_b2(1);

#pragma unroll
    for (int mt = 0; mt < 2; mt++)
#pragma unroll
        for (int nt = 0; nt < 8; nt++)
#pragma unroll
            for (int j = 0; j < 4; j++) acc[mt][nt][j] = 0.f;

    for (int c = 0; c < nch; c++) {
        if (c + 1 < nch) { CP_WAIT(1); } else { CP_WAIT(0); }
        __syncthreads();
        if (c + 2 < nch) issue_b2(c + 2);
        gemm_compute2(sbase + c * ASTG, b2base + (c % NSTAGE) * BSTG, wm, wn, lane, acc);
    }

    // per-row reduction across the 4 wn warp-columns via smem atomics
    __syncthreads();
    float* buf = (float*)smem;
    if (tid < 128) buf[tid] = 0.f;
    __syncthreads();
#pragma unroll
    for (int mt = 0; mt < 2; mt++) {
#pragma unroll
        for (int rr = 0; rr < 2; rr++) {
            int rl = wm * 32 + mt * 16 + rr * 8 + gid;
            float p = 0.f;
#pragma unroll
            for (int nt = 0; nt < 8; nt++) {
                int col = wn * 64 + nt * 8 + ctg * 2;
                float vx = fmaxf(acc[mt][nt][2 * rr] + __ldg(&bias2[col]), 0.f);
                float vy = fmaxf(acc[mt][nt][2 * rr + 1] + __ldg(&bias2[col + 1]), 0.f);
                p += vx * __ldg(&wp3[col]) + vy * __ldg(&wp3[col + 1]);
            }
            p += __shfl_xor_sync(0xFFFFFFFFu, p, 1);
            p += __shfl_xor_sync(0xFFFFFFFFu, p, 2);
            if (ctg == 0) atomicAdd(&buf[rl], p);
        }
    }
    __syncthreads();
    if (tid < 128 && m0 + tid < M_PRED) out[m0 + tid] = buf[tid] + __ldg(&bp3[0]);
}

// ================= host orchestration ==========================================
extern "C" void kernel_launch(void* const* d_in, const int* in_sizes, int n_in,
                              void* d_out, int out_size) {
    const float* x        = (const float*)d_in[0];
    const int*   edge_src = (const int*)d_in[1];
    const int*   edge_dst = (const int*)d_in[2];
    const int*   pos_src  = (const int*)d_in[3];
    const int*   pos_dst  = (const int*)d_in[4];
    const int*   neg_src  = (const int*)d_in[5];
    const int*   neg_dst  = (const int*)d_in[6];
    const float* Ws0 = (const float*)d_in[7];
    const float* Wn0 = (const float*)d_in[8];
    const float* b0  = (const float*)d_in[9];
    const float* Ws1 = (const float*)d_in[10];
    const float* Wn1 = (const float*)d_in[11];
    const float* b1  = (const float*)d_in[12];
    const float* Ws2 = (const float*)d_in[13];
    const float* Wn2 = (const float*)d_in[14];
    const float* b2  = (const float*)d_in[15];
    const float* Wp1 = (const float*)d_in[16];
    const float* bp1 = (const float*)d_in[17];
    const float* Wp2 = (const float*)d_in[18];
    const float* bp2 = (const float*)d_in[19];
    const float* Wp3 = (const float*)d_in[20];
    const float* bp3 = (const float*)d_in[21];
    float* out = (float*)d_out;

    uint8_t *xs, *agg, *h1, *h2, *h3, *wt;
    int* degp;
    cudaGetSymbolAddress((void**)&xs, g_xs);
    cudaGetSymbolAddress((void**)&agg, g_agg);
    cudaGetSymbolAddress((void**)&h1, g_h1);
    cudaGetSymbolAddress((void**)&h2, g_h2);
    cudaGetSymbolAddress((void**)&h3, g_h3);
    cudaGetSymbolAddress((void**)&wt, g_wt);
    cudaGetSymbolAddress((void**)&degp, g_deg);

    cudaFuncSetAttribute(k_gemm_mma, cudaFuncAttributeMaxDynamicSharedMemorySize, GEMM_SMEM);
    cudaFuncSetAttribute(k_pred_fused, cudaFuncAttributeMaxDynamicSharedMemorySize, FUSED_SMEM);

    const int AGG_BLOCKS_DIN = (N_NODES * 16 + 255) / 256;
    const int AGG_BLOCKS_DH  = (N_NODES * 32 + 255) / 256;
    const int NODE_TILES = (N_NODES + 127) / 128;   // 391
    const int PRED_TILES = (M_PRED + 127) / 128;    // 1563

    PrepWAll pw;
    pw.src[0] = Ws0; pw.dst[0] = wt + WT_WS0; pw.K[0] = DIN;
    pw.src[1] = Wn0; pw.dst[1] = wt + WT_WN0; pw.K[1] = DIN;
    pw.src[2] = Ws1; pw.dst[2] = wt + WT_WS1; pw.K[2] = DH;
    pw.src[3] = Wn1; pw.dst[3] = wt + WT_WN1; pw.K[3] = DH;
    pw.src[4] = Ws2; pw.dst[4] = wt + WT_WS2; pw.K[4] = DH;
    pw.src[5] = Wn2; pw.dst[5] = wt + WT_WN2; pw.K[5] = DH;
    pw.src[6] = Wp1; pw.dst[6] = wt + WT_WP1; pw.K[6] = DH;
    pw.src[7] = Wp2; pw.dst[7] = wt + WT_WP2; pw.K[7] = DH;

    // zero degrees via memset node, then merged prep (x split + W prep + count)
    cudaMemsetAsync(degp, 0, N_NODES * sizeof(int), 0);
    k_prep_all<<<PREP0_BLOCKS + PREPW_BLOCKS + COUNT_BLOCKS, 256>>>(x, xs, pw, edge_dst);
    k_scan_block<<<(N_NODES + 1023) / 1024, 1024>>>();
    k_scan_add2<<<(N_NODES + 255) / 256, 256>>>();
    k_scatter<<<(E_EDGES + 255) / 256, 256>>>(edge_src, edge_dst);

    // Layer 0
    k_aggregate<DIN><<<AGG_BLOCKS_DIN, 256>>>(xs, agg);
    k_gemm_mma<<<NODE_TILES, 512, GEMM_SMEM>>>(xs, DIN, wt + WT_WS0, agg, DIN, wt + WT_WN0,
                                               b0, h1, N_NODES, 1);
    // Layer 1
    k_aggregate<DH><<<AGG_BLOCKS_DH, 256>>>(h1, agg);
    k_gemm_mma<<<NODE_TILES, 512, GEMM_SMEM>>>(h1, DH, wt + WT_WS1, agg, DH, wt + WT_WN1,
                                               b1, h2, N_NODES, 1);
    // Layer 2 (no relu)
    k_aggregate<DH><<<AGG_BLOCKS_DH, 256>>>(h2, agg);
    k_gemm_mma<<<NODE_TILES, 512, GEMM_SMEM>>>(h2, DH, wt + WT_WS2, agg, DH, wt + WT_WN2,
                                               b2, h3, N_NODES, 0);

    // Fused predictor (edge GEMM -> relu -> GEMM2 -> final dot)
    k_pred_fused<<<PRED_TILES, 512, FUSED_SMEM>>>(h3, pos_src, pos_dst, neg_src, neg_dst,
                                                  wt + WT_WP1, bp1, wt + WT_WP2, bp2,
                                                  Wp3, bp3, out);
}

// round 16
// speedup vs baseline: 1.0087x; 1.0007x over previous
#include <cuda_runtime.h>
#include <cuda_bf16.h>
#include <cstdint>

#define N_NODES 50000
#define E_EDGES 800000
#define DIN 128
#define DH 256
#define P_PAIRS 100000
#define M_PRED (2 * P_PAIRS)

// ================= helpers =====================================================
__device__ __forceinline__ uint32_t smem_u32(const void* p) {
    uint32_t a;
    asm("{ .reg .u64 t; cvta.to.shared.u64 t, %1; cvt.u32.u64 %0, t; }" : "=r"(a) : "l"(p));
    return a;
}
__device__ __forceinline__ void cp16(uint32_t dst, const void* src, uint32_t sz) {
    asm volatile("cp.async.cg.shared.global [%0], [%1], 16, %2;"
                 :: "r"(dst), "l"(src), "r"(sz) : "memory");
}
__device__ __forceinline__ void cp_commit() {
    asm volatile("cp.async.commit_group;" ::: "memory");
}
#define CP_WAIT(n) asm volatile("cp.async.wait_group %0;" :: "n"(n) : "memory")

__device__ __forceinline__ void ldsm4(uint32_t* r, uint32_t addr) {
    asm volatile("ldmatrix.sync.aligned.m8n8.x4.shared.b16 {%0,%1,%2,%3}, [%4];"
                 : "=r"(r[0]), "=r"(r[1]), "=r"(r[2]), "=r"(r[3]) : "r"(addr));
}
__device__ __forceinline__ void mma_bf16(float* d, const uint32_t* a, const uint32_t* b) {
    asm volatile(
        "mma.sync.aligned.m16n8k16.row.col.f32.bf16.bf16.f32 "
        "{%0,%1,%2,%3}, {%4,%5,%6,%7}, {%8,%9}, {%0,%1,%2,%3};"
        : "+f"(d[0]), "+f"(d[1]), "+f"(d[2]), "+f"(d[3])
        : "r"(a[0]), "r"(a[1]), "r"(a[2]), "r"(a[3]), "r"(b[0]), "r"(b[1]));
}

// split fp32 -> (hi, lo) bf16
__device__ __forceinline__ void split1(float v, uint16_t& h, uint16_t& l) {
    __nv_bfloat16 hb = __float2bfloat16_rn(v);
    float r = v - __bfloat162float(hb);
    __nv_bfloat16 lb = __float2bfloat16_rn(r);
    h = __bfloat16_as_ushort(hb);
    l = __bfloat16_as_ushort(lb);
}
__device__ __forceinline__ void split2(float v0, float v1, uint32_t& hi, uint32_t& lo) {
    uint16_t h0, l0, h1, l1;
    split1(v0, h0, l0); split1(v1, h1, l1);
    hi = (uint32_t)h0 | ((uint32_t)h1 << 16);
    lo = (uint32_t)l0 | ((uint32_t)l1 << 16);
}
__device__ __forceinline__ void split8(const float* v, uint4& hi, uint4& lo) {
    uint32_t h[4], l[4];
#pragma unroll
    for (int i = 0; i < 4; i++) split2(v[2 * i], v[2 * i + 1], h[i], l[i]);
    hi = make_uint4(h[0], h[1], h[2], h[3]);
    lo = make_uint4(l[0], l[1], l[2], l[3]);
}
__device__ __forceinline__ void unpack8(uint4 hi, uint4 lo, float* v) {
    uint32_t hw[4] = {hi.x, hi.y, hi.z, hi.w};
    uint32_t lw[4] = {lo.x, lo.y, lo.z, lo.w};
#pragma unroll
    for (int i = 0; i < 4; i++) {
        v[2 * i]     = __uint_as_float(hw[i] << 16) + __uint_as_float(lw[i] << 16);
        v[2 * i + 1] = __uint_as_float(hw[i] & 0xffff0000u) + __uint_as_float(lw[i] & 0xffff0000u);
    }
}

// Split tensor layout: row r of a [M, K] tensor occupies K*4 bytes:
//   (K/32) blocks of 128B; block = [4 x 16B hi chunks (k=0..31) | 4 x 16B lo chunks]
#define ROWB(K) ((K) * 4)

// ================= scratch =====================================================
__device__ int g_deg[N_NODES];
__device__ int g_off[N_NODES + 1];
__device__ int g_cursor[N_NODES];
__device__ int g_sorted_src[E_EDGES];
__device__ int g_bsum[64];
__device__ __align__(16) uint8_t g_xs[(size_t)N_NODES * DIN * 4];
__device__ __align__(16) uint8_t g_agg[(size_t)N_NODES * DH * 4];
__device__ __align__(16) uint8_t g_h1[(size_t)N_NODES * DH * 4];
__device__ __align__(16) uint8_t g_h2[(size_t)N_NODES * DH * 4];
__device__ __align__(16) uint8_t g_h3[(size_t)N_NODES * DH * 4];
__device__ __align__(16) uint8_t g_wt[1835008];

#define WT_WS0 0
#define WT_WN0 131072
#define WT_WS1 262144
#define WT_WN1 524288
#define WT_WS2 786432
#define WT_WN2 1048576
#define WT_WP1 1310720
#define WT_WP2 1572864

// ================= merged prep: split x + prep W + count deg ===================
struct PrepWAll {
    const float* src[8];
    uint8_t* dst[8];
    int K[8];
};

#define PREP0_BLOCKS 3125          // (N_NODES * 16) / 256
#define PREPW_BLOCKS 256
#define COUNT_BLOCKS 3125          // ceil(E_EDGES / 256)

__global__ void k_prep_all(const float* __restrict__ x, uint8_t* __restrict__ xs,
                           PrepWAll a, const int* __restrict__ edge_dst) {
    int b = blockIdx.x;
    int t = threadIdx.x;
    if (b < PREP0_BLOCKS) {
        int i = b * 256 + t;
        const int units = DIN >> 3;
        if (i < N_NODES * units) {
            int row = i / units, u = i % units;
            const float* src = x + (size_t)row * DIN + u * 8;
            float v[8];
#pragma unroll
            for (int j = 0; j < 8; j++) v[j] = src[j];
            uint4 hi, lo;
            split8(v, hi, lo);
            uint8_t* base = xs + (size_t)row * ROWB(DIN) + (u >> 2) * 128 + (u & 3) * 16;
            *(uint4*)base = hi;
            *(uint4*)(base + 64) = lo;
        }
        return;
    }
    b -= PREP0_BLOCKS;
    if (b < PREPW_BLOCKS) {
        int w = b >> 5;
        int k0 = ((b >> 2) & 7) * 32;
        int n0 = (b & 3) * 64;
        int K = a.K[w];
        if (k0 >= K) return;
        const float* src = a.src[w];
        uint8_t* dst = a.dst[w];
        __shared__ float s[32][65];
#pragma unroll
        for (int l = 0; l < 8; l++) {
            int idx = t + 256 * l;
            int i = idx >> 6, j = idx & 63;
            s[i][j] = src[(size_t)(k0 + i) * DH + n0 + j];
        }
        __syncthreads();
        int n = t >> 2, kc = t & 3;
        float v[8];
#pragma unroll
        for (int q = 0; q < 8; q++) v[q] = s[kc * 8 + q][n];
        uint4 hi, lo;
        split8(v, hi, lo);
        int k = k0 + kc * 8;
        uint8_t* base = dst + (size_t)(n0 + n) * ROWB(K) + (k >> 5) * 128 + ((k >> 3) & 3) * 16;
        *(uint4*)base = hi;
        *(uint4*)(base + 64) = lo;
        return;
    }
    b -= PREPW_BLOCKS;
    {
        int e = b * 256 + t;
        if (e < E_EDGES) atomicAdd(&g_deg[edge_dst[e]], 1);
    }
}

// ================= CSR build ===================================================
__global__ void k_scan_block() {
    __shared__ int s[1024];
    int i = blockIdx.x * 1024 + threadIdx.x;
    int v = (i < N_NODES) ? g_deg[i] : 0;
    s[threadIdx.x] = v;
    __syncthreads();
    for (int ofs = 1; ofs < 1024; ofs <<= 1) {
        int t = (threadIdx.x >= ofs) ? s[threadIdx.x - ofs] : 0;
        __syncthreads();
        s[threadIdx.x] += t;
        __syncthreads();
    }
    if (i < N_NODES) g_off[i] = s[threadIdx.x] - v;
    if (threadIdx.x == 1023) g_bsum[blockIdx.x] = s[1023];
}
__global__ void k_scan_add2() {
    __shared__ int sb[64];
    int tid = threadIdx.x;
    const int nb = (N_NODES + 1023) >> 10;
    if (tid < 64) sb[tid] = (tid < nb) ? g_bsum[tid] : 0;
    __syncthreads();
    for (int ofs = 1; ofs < 64; ofs <<= 1) {
        int t = 0;
        if (tid < 64 && tid >= ofs) t = sb[tid - ofs];
        __syncthreads();
        if (tid < 64) sb[tid] += t;
        __syncthreads();
    }
    int i = blockIdx.x * blockDim.x + tid;
    if (i < N_NODES) {
        int blk = i >> 10;
        int base = blk ? sb[blk - 1] : 0;
        int o = g_off[i] + base;
        g_off[i] = o;
        g_cursor[i] = o;
    }
    if (i == 0) g_off[N_NODES] = E_EDGES;
}
__global__ void k_scatter(const int* __restrict__ src, const int* __restrict__ dst) {
    int e = blockIdx.x * blockDim.x + threadIdx.x;
    if (e < E_EDGES) {
        int d = dst[e];
        int pos = atomicAdd(&g_cursor[d], 1);
        g_sorted_src[pos] = src[e];
    }
}

// ================= mean aggregation (edge loop unrolled x2) ====================
template <int D>
__global__ void k_aggregate(const uint8_t* __restrict__ h, uint8_t* __restrict__ agg) {
    constexpr int GRP = D / 8;
    int gthread = blockIdx.x * blockDim.x + threadIdx.x;
    int node = gthread / GRP;
    int lane = gthread % GRP;
    if (node >= N_NODES) return;
    int s0 = g_off[node], s1 = g_off[node + 1];
    size_t uoff = (size_t)(lane >> 2) * 128 + (lane & 3) * 16;
    float acc[8];
#pragma unroll
    for (int j = 0; j < 8; j++) acc[j] = 0.f;
    int e = s0;
    for (; e + 2 <= s1; e += 2) {
        int sA = g_sorted_src[e];
        int sB = g_sorted_src[e + 1];
        const uint8_t* pA = h + (size_t)sA * ROWB(D) + uoff;
        const uint8_t* pB = h + (size_t)sB * ROWB(D) + uoff;
        uint4 hiA = *(const uint4*)pA;
        uint4 loA = *(const uint4*)(pA + 64);
        uint4 hiB = *(const uint4*)pB;
        uint4 loB = *(const uint4*)(pB + 64);
        float vA[8], vB[8];
        unpack8(hiA, loA, vA);
        unpack8(hiB, loB, vB);
#pragma unroll
        for (int j = 0; j < 8; j++) acc[j] += vA[j] + vB[j];
    }
    if (e < s1) {
        int s = g_sorted_src[e];
        const uint8_t* p = h + (size_t)s * ROWB(D) + uoff;
        uint4 hi = *(const uint4*)p;
        uint4 lo = *(const uint4*)(p + 64);
        float v[8];
        unpack8(hi, lo, v);
#pragma unroll
        for (int j = 0; j < 8; j++) acc[j] += v[j];
    }
    float inv = 1.0f / fmaxf((float)(s1 - s0), 1.0f);
#pragma unroll
    for (int j = 0; j < 8; j++) acc[j] *= inv;
    uint4 hi, lo;
    split8(acc, hi, lo);
    uint8_t* o = agg + (size_t)node * ROWB(D) + uoff;
    *(uint4*)o = hi;
    *(uint4*)(o + 64) = lo;
}

// ================= GEMM building blocks ========================================
#define ASTG 16384                 // A: 128 rows x 128B per 32-k chunk
#define BSTG 32768                 // B: 256 rows x 128B per 32-k chunk
#define STAGE_B (ASTG + BSTG)      // 48KB
#define NSTAGE 3
#define GEMM_SMEM (NSTAGE * STAGE_B)       // 144KB (node GEMM)
#define FUSED_SMEM (131072 + 3 * BSTG)     // 224KB (fused predictor)

__device__ __forceinline__ void gemm_compute2(uint32_t aB, uint32_t bB, int wm, int wn,
                                              int lane, float acc[2][8][4]) {
    int mtx = lane >> 3, rin = lane & 7;
    int aRb = wm * 32 + ((mtx & 1) << 3) + rin;
    int aCb = mtx >> 1;
    int bRb = wn * 64 + ((mtx >> 1) << 3) + rin;
    int bCb = mtx & 1;
#pragma unroll
    for (int ks = 0; ks < 2; ks++) {
        uint32_t ahi[2][4], alo[2][4];
#pragma unroll
        for (int mt = 0; mt < 2; mt++) {
            int r = aRb + mt * 16;
            int ch = aCb + 2 * ks;
            ldsm4(ahi[mt], aB + r * 128 + (uint32_t)((ch ^ (r & 7)) << 4));
            ldsm4(alo[mt], aB + r * 128 + (uint32_t)(((ch + 4) ^ (r & 7)) << 4));
        }
#pragma unroll
        for (int ntp = 0; ntp < 4; ntp++) {
            int r = bRb + ntp * 16;
            int ch = bCb + 2 * ks;
            uint32_t bhi[4], blo[4];
            ldsm4(bhi, bB + r * 128 + (uint32_t)((ch ^ (r & 7)) << 4));
            ldsm4(blo, bB + r * 128 + (uint32_t)(((ch + 4) ^ (r & 7)) << 4));
#pragma unroll
            for (int mt = 0; mt < 2; mt++) {
                mma_bf16(acc[mt][2 * ntp], ahi[mt], bhi);
                mma_bf16(acc[mt][2 * ntp], alo[mt], bhi);
                mma_bf16(acc[mt][2 * ntp], ahi[mt], blo);
                mma_bf16(acc[mt][2 * ntp + 1], ahi[mt], bhi + 2);
                mma_bf16(acc[mt][2 * ntp + 1], alo[mt], bhi + 2);
                mma_bf16(acc[mt][2 * ntp + 1], ahi[mt], blo + 2);
            }
        }
    }
}

__device__ __forceinline__ void gemm_epilogue(int m0, int wm, int wn, int lane,
                                              float acc[2][8][4],
                                              const float* __restrict__ bias,
                                              uint8_t* __restrict__ out, int M, int relu) {
    int gid = lane >> 2, ctg = lane & 3;
#pragma unroll
    for (int mt = 0; mt < 2; mt++) {
        int r0 = m0 + wm * 32 + mt * 16 + gid;
#pragma unroll
        for (int nt = 0; nt < 8; nt++) {
            int col = wn * 64 + nt * 8 + ctg * 2;
            float bx = __ldg(&bias[col]), by = __ldg(&bias[col + 1]);
            size_t coff = (size_t)(col >> 5) * 128 + ((col >> 3) & 3) * 16 + (col & 7) * 2;
#pragma unroll
            for (int rr = 0; rr < 2; rr++) {
                int r = r0 + rr * 8;
                if (r >= M) continue;
                float vx = acc[mt][nt][2 * rr] + bx, vy = acc[mt][nt][2 * rr + 1] + by;
                if (relu) { vx = fmaxf(vx, 0.f); vy = fmaxf(vy, 0.f); }
                uint32_t hi, lo;
                split2(vx, vy, hi, lo);
                uint8_t* base = out + (size_t)r * ROWB(DH) + coff;
                *(uint32_t*)base = hi;
                *(uint32_t*)(base + 64) = lo;
            }
        }
    }
}

// ================= node GEMM: CTA tile 128x256, 512 thr, 3-stage ===============
__global__ __launch_bounds__(512, 1) void k_gemm_mma(
    const uint8_t* __restrict__ A1, int K1, const uint8_t* __restrict__ B1,
    const uint8_t* __restrict__ A2, int K2, const uint8_t* __restrict__ B2,
    const float* __restrict__ bias, uint8_t* __restrict__ out, int M, int relu) {
    extern __shared__ char smem[];
    int tid = threadIdx.x;
    uint32_t sbase = smem_u32(smem);
    int m0 = blockIdx.x * 128;
    int wid = tid >> 5, lane = tid & 31;
    int wm = wid >> 2, wn = wid & 3;

    int nc1 = K1 >> 5;
    int nch = nc1 + (K2 >> 5);
    int srow = tid >> 3, su = tid & 7;

    auto issue = [&](int c) {
        int stage = c % NSTAGE;
        const uint8_t* A; const uint8_t* B; int K, kc;
        if (c < nc1) { A = A1; B = B1; K = K1; kc = c; }
        else         { A = A2; B = B2; K = K2; kc = c - nc1; }
        uint32_t aB = sbase + stage * STAGE_B;
        uint32_t bB = aB + ASTG;
#pragma unroll
        for (int q = 0; q < 2; q++) {
            int row = srow + q * 64;
            uint32_t dst = aB + row * 128 + (uint32_t)((su ^ (row & 7)) << 4);
            int gr = m0 + row;
            uint32_t sz = (gr < M) ? 16u : 0u;
            const uint8_t* src = A + (size_t)(gr < M ? gr : (M - 1)) * ROWB(K) + kc * 128 + su * 16;
            cp16(dst, src, sz);
        }
#pragma unroll
        for (int q = 0; q < 4; q++) {
            int row = srow + q * 64;
            uint32_t dst = bB + row * 128 + (uint32_t)((su ^ (row & 7)) << 4);
            const uint8_t* src = B + (size_t)row * ROWB(K) + kc * 128 + su * 16;
            cp16(dst, src, 16u);
        }
        cp_commit();
    };

    issue(0);
    if (nch > 1) issue(1);

    float acc[2][8][4];
#pragma unroll
    for (int mt = 0; mt < 2; mt++)
#pragma unroll
        for (int nt = 0; nt < 8; nt++)
#pragma unroll
            for (int j = 0; j < 4; j++) acc[mt][nt][j] = 0.f;

    for (int c = 0; c < nch; c++) {
        if (c + 1 < nch) { CP_WAIT(1); } else { CP_WAIT(0); }
        __syncthreads();
        if (c + 2 < nch) issue(c + 2);
        int stage = c % NSTAGE;
        gemm_compute2(sbase + stage * STAGE_B, sbase + stage * STAGE_B + ASTG,
                      wm, wn, lane, acc);
    }
    gemm_epilogue(m0, wm, wn, lane, acc, bias, out, M, relu);
}

// ================= fused predictor: edge GEMM -> relu -> GEMM2 -> dot ==========
__global__ __launch_bounds__(512, 1) void k_pred_fused(
    const uint8_t* __restrict__ h,
    const int* __restrict__ ps, const int* __restrict__ pd,
    const int* __restrict__ ns, const int* __restrict__ nd,
    const uint8_t* __restrict__ B1, const float* __restrict__ bias1,
    const uint8_t* __restrict__ B2, const float* __restrict__ bias2,
    const float* __restrict__ wp3, const float* __restrict__ bp3,
    float* __restrict__ out) {
    extern __shared__ char smem[];
    int tid = threadIdx.x;
    uint32_t sbase = smem_u32(smem);
    int m0 = blockIdx.x * 128;
    int wid = tid >> 5, lane = tid & 31;
    int wm = wid >> 2, wn = wid & 3;
    int gid = lane >> 2, ctg = lane & 3;

    const int nch = DH >> 5;  // 8
    int srow = tid >> 3, su = tid & 7;

    // -------- phase 1: z = relu(h[s]*h[d] @ Wp1 + b1), kept in smem ------------
    int r = tid >> 2, q4 = tid & 3;
    int gr = m0 + r;
    bool valid = gr < M_PRED;
    int s = 0, d = 0;
    if (valid) {
        if (gr < P_PAIRS) { s = ps[gr]; d = pd[gr]; }
        else              { s = ns[gr - P_PAIRS]; d = nd[gr - P_PAIRS]; }
    }
    const uint8_t* rowS = h + (size_t)s * ROWB(DH);
    const uint8_t* rowD = h + (size_t)d * ROWB(DH);

    auto stage_a = [&](int c) {
        int stage = c % NSTAGE;
        uint32_t aB = sbase + stage * STAGE_B;
        int ch = q4;
        float v[8];
        if (valid) {
            const uint8_t* pS = rowS + c * 128 + ch * 16;
            const uint8_t* pD = rowD + c * 128 + ch * 16;
            uint4 shi = *(const uint4*)pS, slo = *(const uint4*)(pS + 64);
            uint4 dhi = *(const uint4*)pD, dlo = *(const uint4*)(pD + 64);
            float sv[8], dv[8];
            unpack8(shi, slo, sv);
            unpack8(dhi, dlo, dv);
#pragma unroll
            for (int j = 0; j < 8; j++) v[j] = sv[j] * dv[j];
        } else {
#pragma unroll
            for (int j = 0; j < 8; j++) v[j] = 0.f;
        }
        uint4 hi, lo;
        split8(v, hi, lo);
        uint32_t dhiA = aB + r * 128 + (uint32_t)((ch ^ (r & 7)) << 4);
        uint32_t dloA = aB + r * 128 + (uint32_t)(((ch + 4) ^ (r & 7)) << 4);
        asm volatile("st.shared.v4.b32 [%0], {%1,%2,%3,%4};"
                     :: "r"(dhiA), "r"(hi.x), "r"(hi.y), "r"(hi.z), "r"(hi.w) : "memory");
        asm volatile("st.shared.v4.b32 [%0], {%1,%2,%3,%4};"
                     :: "r"(dloA), "r"(lo.x), "r"(lo.y), "r"(lo.z), "r"(lo.w) : "memory");
    };
    auto issue_b1 = [&](int c) {
        int stage = c % NSTAGE;
        uint32_t bB = sbase + stage * STAGE_B + ASTG;
#pragma unroll
        for (int q = 0; q < 4; q++) {
            int row = srow + q * 64;
            uint32_t dst = bB + row * 128 + (uint32_t)((su ^ (row & 7)) << 4);
            const uint8_t* src = B1 + (size_t)row * ROWB(DH) + c * 128 + su * 16;
            cp16(dst, src, 16u);
        }
        cp_commit();
    };

    stage_a(0); issue_b1(0);
    stage_a(1); issue_b1(1);

    float acc[2][8][4];
#pragma unroll
    for (int mt = 0; mt < 2; mt++)
#pragma unroll
        for (int nt = 0; nt < 8; nt++)
#pragma unroll
            for (int j = 0; j < 4; j++) acc[mt][nt][j] = 0.f;

    for (int c = 0; c < nch; c++) {
        if (c + 1 < nch) { CP_WAIT(1); } else { CP_WAIT(0); }
        __syncthreads();
        if (c + 2 < nch) { stage_a(c + 2); issue_b1(c + 2); }
        int stage = c % NSTAGE;
        gemm_compute2(sbase + stage * STAGE_B, sbase + stage * STAGE_B + ASTG,
                      wm, wn, lane, acc);
    }

    // -------- inter-phase: write relu(acc + b1) as split-bf16 into smem A ------
    __syncthreads();
#pragma unroll
    for (int mt = 0; mt < 2; mt++) {
#pragma unroll
        for (int nt = 0; nt < 8; nt++) {
            int col = wn * 64 + nt * 8 + ctg * 2;
            float bx = __ldg(&bias1[col]), by = __ldg(&bias1[col + 1]);
            int blk = col >> 5, ch = (col >> 3) & 3, within = (col & 7) * 2;
#pragma unroll
            for (int rr = 0; rr < 2; rr++) {
                int rl = wm * 32 + mt * 16 + rr * 8 + gid;
                float vx = fmaxf(acc[mt][nt][2 * rr] + bx, 0.f);
                float vy = fmaxf(acc[mt][nt][2 * rr + 1] + by, 0.f);
                uint32_t hi, lo;
                split2(vx, vy, hi, lo);
                uint32_t base = sbase + blk * ASTG + rl * 128;
                uint32_t ahiA = base + (uint32_t)((ch ^ (rl & 7)) << 4) + within;
                uint32_t aloA = base + (uint32_t)(((ch + 4) ^ (rl & 7)) << 4) + within;
                asm volatile("st.shared.b32 [%0], %1;" :: "r"(ahiA), "r"(hi) : "memory");
                asm volatile("st.shared.b32 [%0], %1;" :: "r"(aloA), "r"(lo) : "memory");
            }
        }
    }
    __syncthreads();

    // -------- phase 2: acc2 = z @ Wp2 ; out = relu(acc2+b2) . wp3 + bp3 --------
    uint32_t b2base = sbase + 131072;
    auto issue_b2 = [&](int c) {
        int stage = c % NSTAGE;
        uint32_t bB = b2base + stage * BSTG;
#pragma unroll
        for (int q = 0; q < 4; q++) {
            int row = srow + q * 64;
            uint32_t dst = bB + row * 128 + (uint32_t)((su ^ (row & 7)) << 4);
            const uint8_t* src = B2 + (size_t)row * ROWB(DH) + c * 128 + su * 16;
            cp16(dst, src, 16u);
        }
        cp_commit();
    };

    issue_b2(0);
    issue_b2(1);

#pragma unroll
    for (int mt = 0; mt < 2; mt++)
#pragma unroll
        for (int nt = 0; nt < 8; nt++)
#pragma unroll
            for (int j = 0; j < 4; j++) acc[mt][nt][j] = 0.f;

    for (int c = 0; c < nch; c++) {
        if (c + 1 < nch) { CP_WAIT(1); } else { CP_WAIT(0); }
        __syncthreads();
        if (c + 2 < nch) issue_b2(c + 2);
        gemm_compute2(sbase + c * ASTG, b2base + (c % NSTAGE) * BSTG, wm, wn, lane, acc);
    }

    // per-row reduction across the 4 wn warp-columns via smem atomics
    __syncthreads();
    float* buf = (float*)smem;
    if (tid < 128) buf[tid] = 0.f;
    __syncthreads();
#pragma unroll
    for (int mt = 0; mt < 2; mt++) {
#pragma unroll
        for (int rr = 0; rr < 2; rr++) {
            int rl = wm * 32 + mt * 16 + rr * 8 + gid;
            float p = 0.f;
#pragma unroll
            for (int nt = 0; nt < 8; nt++) {
                int col = wn * 64 + nt * 8 + ctg * 2;
                float vx = fmaxf(acc[mt][nt][2 * rr] + __ldg(&bias2[col]), 0.f);
                float vy = fmaxf(acc[mt][nt][2 * rr + 1] + __ldg(&bias2[col + 1]), 0.f);
                p += vx * __ldg(&wp3[col]) + vy * __ldg(&wp3[col + 1]);
            }
            p += __shfl_xor_sync(0xFFFFFFFFu, p, 1);
            p += __shfl_xor_sync(0xFFFFFFFFu, p, 2);
            if (ctg == 0) atomicAdd(&buf[rl], p);
        }
    }
    __syncthreads();
    if (tid < 128 && m0 + tid < M_PRED) out[m0 + tid] = buf[tid] + __ldg(&bp3[0]);
}

// ================= host orchestration ==========================================
extern "C" void kernel_launch(void* const* d_in, const int* in_sizes, int n_in,
                              void* d_out, int out_size) {
    const float* x        = (const float*)d_in[0];
    const int*   edge_src = (const int*)d_in[1];
    const int*   edge_dst = (const int*)d_in[2];
    const int*   pos_src  = (const int*)d_in[3];
    const int*   pos_dst  = (const int*)d_in[4];
    const int*   neg_src  = (const int*)d_in[5];
    const int*   neg_dst  = (const int*)d_in[6];
    const float* Ws0 = (const float*)d_in[7];
    const float* Wn0 = (const float*)d_in[8];
    const float* b0  = (const float*)d_in[9];
    const float* Ws1 = (const float*)d_in[10];
    const float* Wn1 = (const float*)d_in[11];
    const float* b1  = (const float*)d_in[12];
    const float* Ws2 = (const float*)d_in[13];
    const float* Wn2 = (const float*)d_in[14];
    const float* b2  = (const float*)d_in[15];
    const float* Wp1 = (const float*)d_in[16];
    const float* bp1 = (const float*)d_in[17];
    const float* Wp2 = (const float*)d_in[18];
    const float* bp2 = (const float*)d_in[19];
    const float* Wp3 = (const float*)d_in[20];
    const float* bp3 = (const float*)d_in[21];
    float* out = (float*)d_out;

    uint8_t *xs, *agg, *h1, *h2, *h3, *wt;
    int* degp;
    cudaGetSymbolAddress((void**)&xs, g_xs);
    cudaGetSymbolAddress((void**)&agg, g_agg);
    cudaGetSymbolAddress((void**)&h1, g_h1);
    cudaGetSymbolAddress((void**)&h2, g_h2);
    cudaGetSymbolAddress((void**)&h3, g_h3);
    cudaGetSymbolAddress((void**)&wt, g_wt);
    cudaGetSymbolAddress((void**)&degp, g_deg);

    cudaFuncSetAttribute(k_gemm_mma, cudaFuncAttributeMaxDynamicSharedMemorySize, GEMM_SMEM);
    cudaFuncSetAttribute(k_pred_fused, cudaFuncAttributeMaxDynamicSharedMemorySize, FUSED_SMEM);

    const int AGG_BLOCKS_DIN = (N_NODES * 16 + 255) / 256;
    const int AGG_BLOCKS_DH  = (N_NODES * 32 + 255) / 256;
    const int NODE_TILES = (N_NODES + 127) / 128;   // 391
    const int PRED_TILES = (M_PRED + 127) / 128;    // 1563

    PrepWAll pw;
    pw.src[0] = Ws0; pw.dst[0] = wt + WT_WS0; pw.K[0] = DIN;
    pw.src[1] = Wn0; pw.dst[1] = wt + WT_WN0; pw.K[1] = DIN;
    pw.src[2] = Ws1; pw.dst[2] = wt + WT_WS1; pw.K[2] = DH;
    pw.src[3] = Wn1; pw.dst[3] = wt + WT_WN1; pw.K[3] = DH;
    pw.src[4] = Ws2; pw.dst[4] = wt + WT_WS2; pw.K[4] = DH;
    pw.src[5] = Wn2; pw.dst[5] = wt + WT_WN2; pw.K[5] = DH;
    pw.src[6] = Wp1; pw.dst[6] = wt + WT_WP1; pw.K[6] = DH;
    pw.src[7] = Wp2; pw.dst[7] = wt + WT_WP2; pw.K[7] = DH;

    // zero degrees via memset node, then merged prep (x split + W prep + count)
    cudaMemsetAsync(degp, 0, N_NODES * sizeof(int), 0);
    k_prep_all<<<PREP0_BLOCKS + PREPW_BLOCKS + COUNT_BLOCKS, 256>>>(x, xs, pw, edge_dst);
    k_scan_block<<<(N_NODES + 1023) / 1024, 1024>>>();
    k_scan_add2<<<(N_NODES + 255) / 256, 256>>>();
    k_scatter<<<(E_EDGES + 255) / 256, 256>>>(edge_src, edge_dst);

    // Layer 0
    k_aggregate<DIN><<<AGG_BLOCKS_DIN, 256>>>(xs, agg);
    k_gemm_mma<<<NODE_TILES, 512, GEMM_SMEM>>>(xs, DIN, wt + WT_WS0, agg, DIN, wt + WT_WN0,
                                               b0, h1, N_NODES, 1);
    // Layer 1
    k_aggregate<DH><<<AGG_BLOCKS_DH, 256>>>(h1, agg);
    k_gemm_mma<<<NODE_TILES, 512, GEMM_SMEM>>>(h1, DH, wt + WT_WS1, agg, DH, wt + WT_WN1,
                                               b1, h2, N_NODES, 1);
    // Layer 2 (no relu)
    k_aggregate<DH><<<AGG_BLOCKS_DH, 256>>>(h2, agg);
    k_gemm_mma<<<NODE_TILES, 512, GEMM_SMEM>>>(h2, DH, wt + WT_WS2, agg, DH, wt + WT_WN2,
                                               b2, h3, N_NODES, 0);

    // Fused predictor (edge GEMM -> relu -> GEMM2 -> final dot)
    k_pred_fused<<<PRED_TILES, 512, FUSED_SMEM>>>(h3, pos_src, pos_dst, neg_src, neg_dst,
                                                  wt + WT_WP1, bp1, wt + WT_WP2, bp2,
                                                  Wp3, bp3, out);
}